// round 10
// baseline (speedup 1.0000x reference)
#include <cuda_runtime.h>
#include <cuda_bf16.h>

// Problem shape (fixed by dataset):
//   S = 8192  source codes
//   G = 1024  groups
//   T = 4096  time segments (t0 sorted ascending)
//   E = 16384 events
//
// out[t, g] = sum over events with start <= t0[t] < end of
//             rate[e] * weights[index[e]], grouped by group_id[index[e]].
//
// t0 sorted -> each event is two difference-array endpoints (+w at lo, -w at
// hi). Pipeline (memset + 3 kernels):
//   0. memsetAsync(d_out)  -- d_out doubles as the 16MB difference array.
//   1. scatter: exact binary search, fire-and-forget REDG atomics: +-w into
//      out[row][g] (row-level diff) AND +-w into g_part[g][chunk]
//      (chunk-level column sums -- fuses the old chunk_sum pass for free).
//   2. scan: warp-per-column shuffle scan of g_part -> exclusive chunk
//      offsets transposed into g_off[c][g]; zero-restores g_part.
//   3. apply: per chunk, prefetch 8 rows (MLP-8), running prefix seeded by
//      coalesced g_off read, write back in place.

#define T_DIM 4096
#define G_DIM 1024
#define G4    (G_DIM / 4)     // 256 float4 columns
#define CH    8               // rows per chunk
#define NCH   (T_DIM / CH)    // 512 chunks

// Bank-conflict-breaking bijection on [0,4096): x ^ (x>>5) ^ (x>>10)
// (GF(2)-linear, invertible; power-of-2 probe strides >=32 hit distinct banks)
#define SWZ(m) ((m) ^ ((m) >> 5) ^ ((m) >> 10))

__device__ float g_part[G_DIM][NCH];     // chunk column sums, 2 MB (zero inv.)
__device__ float g_off[NCH][G_DIM];      // exclusive offsets, chunk-major, 2 MB

// ---------------------------------------------------------------------------
// Kernel 1: per-event binary search -> 4 fire-and-forget atomics
// ---------------------------------------------------------------------------
__global__ void __launch_bounds__(256)
scatter_kernel(const int* __restrict__ index,
               const float* __restrict__ rate,
               const float* __restrict__ starttime,
               const float* __restrict__ endtime,
               const float* __restrict__ t0,
               const int* __restrict__ group_id,
               const float* __restrict__ weights,
               float* __restrict__ out,
               int E)
{
    __shared__ float sh_t0[T_DIM];
    for (int i = threadIdx.x; i < T_DIM; i += 256)
        sh_t0[SWZ(i)] = t0[i];

    int e = blockIdx.x * 256 + threadIdx.x;

    // Prefetch event data before the search (overlaps the LDS chains)
    float st = 0.f, en = 0.f, rt = 0.f, wgt = 0.f;
    int g = 0;
    bool valid = (e < E);
    if (valid) {
        st = starttime[e];
        en = endtime[e];
        rt = rate[e];
        int src = index[e];
        wgt = weights[src];
        g   = group_id[src];
    }
    __syncthreads();

    if (!valid) return;

    // Two independent exact lower_bounds (first idx with t0[idx] >= x),
    // interleaved for ILP-2 on the LDS chains.
    int lo = 0, hi = T_DIM, lo2 = 0, hi2 = T_DIM;
    while (lo < hi && lo2 < hi2) {
        int m1 = (lo + hi) >> 1;
        int m2 = (lo2 + hi2) >> 1;
        float a = sh_t0[SWZ(m1)];
        float b = sh_t0[SWZ(m2)];
        if (a < st) lo = m1 + 1; else hi = m1;
        if (b < en) lo2 = m2 + 1; else hi2 = m2;
    }
    while (lo < hi) {
        int m = (lo + hi) >> 1;
        if (sh_t0[SWZ(m)] < st) lo = m + 1; else hi = m;
    }
    while (lo2 < hi2) {
        int m = (lo2 + hi2) >> 1;
        if (sh_t0[SWZ(m)] < en) lo2 = m + 1; else hi2 = m;
    }
    // active time-index range is [lo, lo2)
    if (lo >= lo2) return;

    float w = rt * wgt;

    // Row-level endpoints into the output-resident diff array
    atomicAdd(&out[lo * G_DIM + g], w);
    atomicAdd(&g_part[g][lo >> 3], w);
    if (lo2 < T_DIM) {
        atomicAdd(&out[lo2 * G_DIM + g], -w);
        atomicAdd(&g_part[g][lo2 >> 3], -w);
    }
}

// ---------------------------------------------------------------------------
// Kernel 2: exclusive scan of chunk sums per column; warp = one column.
// Block = 16 warps (16 columns), grid = 64. Results transposed through smem
// to g_off[c][g] (chunk-major -> coalesced in apply). Restores g_part to 0.
// ---------------------------------------------------------------------------
__global__ void __launch_bounds__(512)
scan_kernel()
{
    __shared__ float sh[NCH][17];        // [c][warp], padded
    int warp = threadIdx.x >> 5;
    int lane = threadIdx.x & 31;
    int g = blockIdx.x * 16 + warp;

    // lane owns chunks [lane*16, lane*16+16)
    float4* base = (float4*)&g_part[g][lane * 16];
    float v[16];
    #pragma unroll
    for (int q = 0; q < 4; q++) {
        float4 x = base[q];
        v[q*4+0] = x.x; v[q*4+1] = x.y; v[q*4+2] = x.z; v[q*4+3] = x.w;
    }
    // restore zero invariant for next replay
    float4 z = make_float4(0.f, 0.f, 0.f, 0.f);
    #pragma unroll
    for (int q = 0; q < 4; q++) base[q] = z;

    // per-lane total, then warp exclusive scan of totals
    float tot = 0.f;
    #pragma unroll
    for (int i = 0; i < 16; i++) tot += v[i];
    float acc = tot;
    #pragma unroll
    for (int off = 1; off < 32; off <<= 1) {
        float up = __shfl_up_sync(0xFFFFFFFFu, acc, off);
        if (lane >= off) acc += up;
    }
    float excl = acc - tot;              // exclusive prefix of lane totals

    // per-chunk exclusive prefixes into the transpose tile
    float run = excl;
    #pragma unroll
    for (int i = 0; i < 16; i++) {
        sh[lane * 16 + i][warp] = run;
        run += v[i];
    }
    __syncthreads();

    // write transposed: thread = chunk c, 16 contiguous floats (4x float4)
    int c = threadIdx.x;
    float4* dst = (float4*)&g_off[c][blockIdx.x * 16];
    #pragma unroll
    for (int q = 0; q < 4; q++)
        dst[q] = make_float4(sh[c][q*4+0], sh[c][q*4+1],
                             sh[c][q*4+2], sh[c][q*4+3]);
}

// ---------------------------------------------------------------------------
// Kernel 3: apply. Block = chunk. Prefetch all 8 rows of this thread's
// float4 column (independent loads, MLP-8), then an 8-deep FADD prefix
// seeded by the coalesced chunk offset, then 8 stores. In-place on out.
// ---------------------------------------------------------------------------
__global__ void __launch_bounds__(256)
apply_kernel(float4* __restrict__ out)
{
    int c = blockIdx.x;                  // chunk 0..511
    int t = threadIdx.x;                 // float4 column 0..255

    float4* p = out + (size_t)c * CH * G4 + t;

    float4 v[CH];
    #pragma unroll
    for (int r = 0; r < CH; r++)
        v[r] = p[r * G4];

    float4 run = *(const float4*)&g_off[c][4 * t];
    #pragma unroll
    for (int r = 0; r < CH; r++) {
        run.x += v[r].x; run.y += v[r].y; run.z += v[r].z; run.w += v[r].w;
        v[r] = run;
    }

    #pragma unroll
    for (int r = 0; r < CH; r++)
        p[r * G4] = v[r];
}

// ---------------------------------------------------------------------------
extern "C" void kernel_launch(void* const* d_in, const int* in_sizes, int n_in,
                              void* d_out, int out_size)
{
    const int*   index     = (const int*)  d_in[0];
    const float* rate      = (const float*)d_in[1];
    const float* starttime = (const float*)d_in[2];
    const float* endtime   = (const float*)d_in[3];
    const float* t0        = (const float*)d_in[4];
    const int*   group_id  = (const int*)  d_in[5];
    const float* weights   = (const float*)d_in[6];
    float*       out       = (float*)d_out;

    int E = in_sizes[0];

    cudaMemsetAsync(d_out, 0, (size_t)out_size * sizeof(float), 0);

    scatter_kernel<<<(E + 255) / 256, 256>>>(index, rate, starttime, endtime,
                                             t0, group_id, weights, out, E);

    scan_kernel<<<G_DIM / 16, 512>>>();

    apply_kernel<<<NCH, 256>>>((float4*)d_out);
}